// round 10
// baseline (speedup 1.0000x reference)
#include <cuda_runtime.h>
#include <stdint.h>

// SpikeFP8Adder_Spatial: soft-logic E4M3 adder on {0,1}-valued float bit vectors.
// Exact 0/1 inputs => gate network collapses to integer bit logic (1 output byte/row).
// R10: split into two near-unidirectional HBM streams to avoid read/write turnaround:
//   phase1: 256MB pure read -> 4MB byte-packed scratch (stays in L2, __stcg)
//   phase2: 4MB L2 read -> 128MB pure write
// Fused R2-style kernel kept as fallback for nrows > scratch capacity.

#define SCRATCH_ROWS 4194304
__device__ uint8_t g_scratch[SCRATCH_ROWS];

__device__ __forceinline__ unsigned pack8(const uint4& v0, const uint4& v1)
{
    // MSB-first byte from 8 floats (1.0f = 0x3F800000, bit 23 set).
    return (((v0.x >> 23) & 1u) << 7) | (((v0.y >> 23) & 1u) << 6) |
           (((v0.z >> 23) & 1u) << 5) | (((v0.w >> 23) & 1u) << 4) |
           (((v1.x >> 23) & 1u) << 3) | (((v1.y >> 23) & 1u) << 2) |
           (((v1.z >> 23) & 1u) << 1) |  ((v1.w >> 23) & 1u);
}

__device__ __forceinline__ unsigned fp8add_byte(unsigned pa, unsigned pb)
{
    unsigned sa = (pa >> 7) & 1u, ea = (pa >> 3) & 15u, ma = pa & 7u;
    unsigned sb = (pb >> 7) & 1u, eb = (pb >> 3) & 15u, mb = pb & 7u;

    bool sel = (ea >= eb);
    unsigned el = sel ? ea : eb;
    unsigned es = sel ? eb : ea;
    unsigned ml = sel ? ma : mb;
    unsigned ms = sel ? mb : ma;
    unsigned sl = sel ? sa : sb;
    unsigned ss = sel ? sb : sa;

    unsigned diff = el - es;

    unsigned extl = ((el != 0u) ? 0x400u : 0u) | (ml << 7);
    unsigned exts = (((es != 0u) ? 0x400u : 0u) | (ms << 7)) >> diff;

    unsigned mant = (sl == ss) ? ((extl + exts) & 0xFFFu)
                               : ((extl - exts) & 0xFFFu);

    unsigned top8 = mant >> 4;
    unsigned lzc = top8 ? (unsigned)(__clz((int)top8) - 24) : 7u;
    unsigned norm = (top8 << lzc) & 0xFFu;
    unsigned en = (el - lzc + 1u) & 15u;

    return (sl << 7) | (en << 3) | ((norm >> 4) & 7u);
}

__device__ __forceinline__ void expand_byte(unsigned ob, uint4& o0, uint4& o1)
{
    const unsigned ONE = 0x3F800000u;
    o0.x = ((ob >> 7) & 1u) * ONE;
    o0.y = ((ob >> 6) & 1u) * ONE;
    o0.z = ((ob >> 5) & 1u) * ONE;
    o0.w = ((ob >> 4) & 1u) * ONE;
    o1.x = ((ob >> 3) & 1u) * ONE;
    o1.y = ((ob >> 2) & 1u) * ONE;
    o1.z = ((ob >> 1) & 1u) * ONE;
    o1.w = ( ob        & 1u) * ONE;
}

// Phase 1: pure-read stream. 2 rows/thread (strided halves), 8 front-batched loads.
__global__ __launch_bounds__(256) void fp8_phase1(
    const uint4* __restrict__ A,
    const uint4* __restrict__ B,
    int half)
{
    int i = blockIdx.x * blockDim.x + threadIdx.x;
    if (i >= half) return;
    int j = i + half;

    uint4 a0 = __ldcs(&A[2 * i + 0]);
    uint4 a1 = __ldcs(&A[2 * i + 1]);
    uint4 b0 = __ldcs(&B[2 * i + 0]);
    uint4 b1 = __ldcs(&B[2 * i + 1]);
    uint4 c0 = __ldcs(&A[2 * j + 0]);
    uint4 c1 = __ldcs(&A[2 * j + 1]);
    uint4 d0 = __ldcs(&B[2 * j + 0]);
    uint4 d1 = __ldcs(&B[2 * j + 1]);

    unsigned ob0 = fp8add_byte(pack8(a0, a1), pack8(b0, b1));
    unsigned ob1 = fp8add_byte(pack8(c0, c1), pack8(d0, d1));

    // Tiny writes, keep in L2 (evict-last-ish via .cg: caches at L2, no L1).
    __stcg(&g_scratch[i], (uint8_t)ob0);
    __stcg(&g_scratch[j], (uint8_t)ob1);
}

// Phase 2: pure-write stream. 2 rows/thread; scratch read is an L2 hit.
__global__ __launch_bounds__(256) void fp8_phase2(
    uint4* __restrict__ O,
    int half)
{
    int i = blockIdx.x * blockDim.x + threadIdx.x;
    if (i >= half) return;
    int j = i + half;

    unsigned ob0 = __ldcg(&g_scratch[i]);
    unsigned ob1 = __ldcg(&g_scratch[j]);

    uint4 o0, o1;
    expand_byte(ob0, o0, o1);
    __stcs(&O[2 * i + 0], o0);
    __stcs(&O[2 * i + 1], o1);

    expand_byte(ob1, o0, o1);
    __stcs(&O[2 * j + 0], o0);
    __stcs(&O[2 * j + 1], o1);
}

// Fused fallback (R2 config) for rows beyond scratch capacity / odd tail.
__global__ __launch_bounds__(256) void fp8add_fused(
    const uint4* __restrict__ A,
    const uint4* __restrict__ B,
    uint4* __restrict__ O,
    int nrows, int start)
{
    int i = start + blockIdx.x * blockDim.x + threadIdx.x;
    if (i >= nrows) return;
    uint4 a0 = __ldcs(&A[2 * i + 0]);
    uint4 a1 = __ldcs(&A[2 * i + 1]);
    uint4 b0 = __ldcs(&B[2 * i + 0]);
    uint4 b1 = __ldcs(&B[2 * i + 1]);
    unsigned ob = fp8add_byte(pack8(a0, a1), pack8(b0, b1));
    uint4 o0, o1;
    expand_byte(ob, o0, o1);
    __stcs(&O[2 * i + 0], o0);
    __stcs(&O[2 * i + 1], o1);
}

extern "C" void kernel_launch(void* const* d_in, const int* in_sizes, int n_in,
                              void* d_out, int out_size)
{
    const uint4* A = (const uint4*)d_in[0];
    const uint4* B = (const uint4*)d_in[1];
    uint4* O = (uint4*)d_out;

    int nrows = in_sizes[0] / 8;
    int threads = 256;

    int main_rows = (nrows <= SCRATCH_ROWS) ? nrows : SCRATCH_ROWS;
    int half = main_rows >> 1;

    if (half > 0) {
        int blocks = (half + threads - 1) / threads;
        fp8_phase1<<<blocks, threads>>>(A, B, half);
        fp8_phase2<<<blocks, threads>>>(O, half);
    }
    int done = half << 1;
    if (done < nrows) {
        int rem = nrows - done;
        int blocks = (rem + threads - 1) / threads;
        fp8add_fused<<<blocks, threads>>>(A, B, O, nrows, done);
    }
}

// round 11
// speedup vs baseline: 1.3566x; 1.3566x over previous
#include <cuda_runtime.h>
#include <stdint.h>

// SpikeFP8Adder_Spatial: soft-logic E4M3 adder on {0,1}-valued float bit vectors.
// Exact 0/1 inputs => gate network collapses to integer bit logic.
// Pure HBM-bound (384 MB irreducible traffic). Final config (R2): 2 rows/thread
// (strided halves), 8 front-batched streaming loads, fire-and-exit CTAs.
// Measured at 6.48 TB/s = the chip's path-independent LTS/DRAM cap; sweeps of
// occupancy, MLP depth, coalescing width, persistence, and stream separation
// (R3-R10) all confirmed this is the roofline.

__device__ __forceinline__ void fp8add_row(
    const uint4& a0, const uint4& a1,
    const uint4& b0, const uint4& b1,
    uint4& o0, uint4& o1)
{
    // Pack MSB-first: index 0 -> bit7 ... index 7 -> bit0. 1.0f = 0x3F800000 (bit 23 set).
    unsigned pa =
        (((a0.x >> 23) & 1u) << 7) | (((a0.y >> 23) & 1u) << 6) |
        (((a0.z >> 23) & 1u) << 5) | (((a0.w >> 23) & 1u) << 4) |
        (((a1.x >> 23) & 1u) << 3) | (((a1.y >> 23) & 1u) << 2) |
        (((a1.z >> 23) & 1u) << 1) |  ((a1.w >> 23) & 1u);
    unsigned pb =
        (((b0.x >> 23) & 1u) << 7) | (((b0.y >> 23) & 1u) << 6) |
        (((b0.z >> 23) & 1u) << 5) | (((b0.w >> 23) & 1u) << 4) |
        (((b1.x >> 23) & 1u) << 3) | (((b1.y >> 23) & 1u) << 2) |
        (((b1.z >> 23) & 1u) << 1) |  ((b1.w >> 23) & 1u);

    unsigned sa = (pa >> 7) & 1u, ea = (pa >> 3) & 15u, ma = pa & 7u;
    unsigned sb = (pb >> 7) & 1u, eb = (pb >> 3) & 15u, mb = pb & 7u;

    // Comparator4: sel = (ea >= eb)
    bool sel = (ea >= eb);
    unsigned el = sel ? ea : eb;
    unsigned es = sel ? eb : ea;
    unsigned ml = sel ? ma : mb;
    unsigned ms = sel ? mb : ma;
    unsigned sl = sel ? sa : sb;
    unsigned ss = sel ? sb : sa;

    unsigned diff = el - es;

    // 12-bit extended mantissas: hidden at bit 10, mantissa at bits 9..7.
    unsigned extl = ((el != 0u) ? 0x400u : 0u) | (ml << 7);
    unsigned exts = (((es != 0u) ? 0x400u : 0u) | (ms << 7)) >> diff;

    // 12-bit add/sub with wrap (matches ripple carry/borrow mod 4096).
    unsigned mant = (sl == ss) ? ((extl + exts) & 0xFFFu)
                               : ((extl - exts) & 0xFFFu);

    unsigned top8 = mant >> 4;

    // LZD8: clz over 8 bits, saturating at 7 for zero input.
    unsigned lzc = top8 ? (unsigned)(__clz((int)top8) - 24) : 7u;

    unsigned norm = (top8 << lzc) & 0xFFu;

    // exp_new = (el - lzc + 1) mod 16
    unsigned en = (el - lzc + 1u) & 15u;

    const unsigned ONE = 0x3F800000u;
    o0.x = sl * ONE;
    o0.y = ((en >> 3) & 1u) * ONE;
    o0.z = ((en >> 2) & 1u) * ONE;
    o0.w = ((en >> 1) & 1u) * ONE;
    o1.x = (en & 1u) * ONE;
    o1.y = ((norm >> 6) & 1u) * ONE;
    o1.z = ((norm >> 5) & 1u) * ONE;
    o1.w = ((norm >> 4) & 1u) * ONE;
}

__global__ __launch_bounds__(256) void fp8add_kernel2(
    const uint4* __restrict__ A,
    const uint4* __restrict__ B,
    uint4* __restrict__ O,
    int half)   // nrows / 2
{
    int i = blockIdx.x * blockDim.x + threadIdx.x;
    if (i >= half) return;
    int j = i + half;

    // Front-batch all 8 loads (streaming, evict-first) for maximum MLP.
    uint4 a0 = __ldcs(&A[2 * i + 0]);
    uint4 a1 = __ldcs(&A[2 * i + 1]);
    uint4 b0 = __ldcs(&B[2 * i + 0]);
    uint4 b1 = __ldcs(&B[2 * i + 1]);
    uint4 c0 = __ldcs(&A[2 * j + 0]);
    uint4 c1 = __ldcs(&A[2 * j + 1]);
    uint4 d0 = __ldcs(&B[2 * j + 0]);
    uint4 d1 = __ldcs(&B[2 * j + 1]);

    uint4 o0, o1, p0, p1;
    fp8add_row(a0, a1, b0, b1, o0, o1);
    fp8add_row(c0, c1, d0, d1, p0, p1);

    __stcs(&O[2 * i + 0], o0);
    __stcs(&O[2 * i + 1], o1);
    __stcs(&O[2 * j + 0], p0);
    __stcs(&O[2 * j + 1], p1);
}

__global__ __launch_bounds__(256) void fp8add_kernel1(
    const uint4* __restrict__ A,
    const uint4* __restrict__ B,
    uint4* __restrict__ O,
    int nrows, int start)
{
    int i = start + blockIdx.x * blockDim.x + threadIdx.x;
    if (i >= nrows) return;
    uint4 a0 = __ldcs(&A[2 * i + 0]);
    uint4 a1 = __ldcs(&A[2 * i + 1]);
    uint4 b0 = __ldcs(&B[2 * i + 0]);
    uint4 b1 = __ldcs(&B[2 * i + 1]);
    uint4 o0, o1;
    fp8add_row(a0, a1, b0, b1, o0, o1);
    __stcs(&O[2 * i + 0], o0);
    __stcs(&O[2 * i + 1], o1);
}

extern "C" void kernel_launch(void* const* d_in, const int* in_sizes, int n_in,
                              void* d_out, int out_size)
{
    const uint4* A = (const uint4*)d_in[0];
    const uint4* B = (const uint4*)d_in[1];
    uint4* O = (uint4*)d_out;

    int nrows = in_sizes[0] / 8;
    int half = nrows >> 1;
    int threads = 256;

    if (half > 0) {
        int blocks = (half + threads - 1) / threads;
        fp8add_kernel2<<<blocks, threads>>>(A, B, O, half);
    }
    if (nrows & 1) {
        // odd tail row (not hit for N=4194304, kept for generality)
        fp8add_kernel1<<<1, 1>>>(A, B, O, nrows, nrows - 1);
    }
}